// round 14
// baseline (speedup 1.0000x reference)
#include <cuda_runtime.h>
#include <math_constants.h>

#define B_   8
#define N_   4096
#define F_   64
#define P_   1024
#define K_   16
#define CPF_ 32
#define CF_  96      // CPF + F
#define C_   128
#define DM_  2
#define KK_  256     // K*K
#define EPS_ 0.001f
#define M_   4       // points per block in point_kernel
#define PT_  256     // point_kernel threads

// knn smem: sx/sy/sz (3 x 16KB) + per-warp candidate buffers (8 x 64 x 8B)
#define KNN_SMEM (49152 + 8 * 64 * 8)

// Scratch for kNN indices (allocation-free rule: __device__ global)
__device__ int g_idx[B_ * P_ * K_];

// ---------------------------------------------------------------------------
// kNN: warp per query, batched top-32 (R13 bitonic flush).
// FROZEN numerics: dot = k-ordered FMA chain; pn = rn(rn(x^2+y^2)+z^2)
// (recomputed in-loop, bit-identical to cached); d2 = (qn - 2*dot) + pn;
// TOTAL ORDER = lexicographic (d2, index).
// R14: SoA point cache (sx/sy/sz) -> 3 LDS wavefronts/iter (was 4) and
// 48KB cache -> 4 blocks/SM (was 3).
// ---------------------------------------------------------------------------
__device__ __forceinline__ bool lex_gt(float a, int ai, float b, int bi) {
    return (a > b) || (a == b && ai > bi);
}

// Sort 32 (sd,si) across lanes ascending-lex, then merge top-32 into (ld,li).
__device__ __forceinline__ void topk_flush(float& ld, int& li, float sd, int si,
                                           int lane) {
    const unsigned FULL = 0xffffffffu;
    #pragma unroll
    for (int k = 2; k <= 32; k <<= 1) {
        #pragma unroll
        for (int j = k >> 1; j > 0; j >>= 1) {
            float od = __shfl_xor_sync(FULL, sd, j);
            int   oi = __shfl_xor_sync(FULL, si, j);
            bool up    = ((lane & k) == 0);
            bool lower = ((lane & j) == 0);
            bool gt = lex_gt(sd, si, od, oi);
            bool takeOther = up ? (lower ? gt : !gt) : (lower ? !gt : gt);
            if (takeOther) { sd = od; si = oi; }
        }
    }
    {
        float rd = __shfl_xor_sync(FULL, sd, 31);
        int   ri = __shfl_xor_sync(FULL, si, 31);
        if (lex_gt(ld, li, rd, ri)) { ld = rd; li = ri; }
    }
    #pragma unroll
    for (int j = 16; j > 0; j >>= 1) {
        float od = __shfl_xor_sync(FULL, ld, j);
        int   oi = __shfl_xor_sync(FULL, li, j);
        bool lower = ((lane & j) == 0);
        bool gt = lex_gt(ld, li, od, oi);
        bool takeOther = lower ? gt : !gt;
        if (takeOther) { ld = od; li = oi; }
    }
}

__global__ void knn_kernel(const float* __restrict__ pts, float* __restrict__ out) {
    extern __shared__ float sm[];
    float* sx   = sm;                    // 4096
    float* sy   = sm + 4096;
    float* sz   = sm + 8192;
    float* bufd = sm + 12288;            // 8 warps x 64
    int*   bufi = (int*)(sm + 12288 + 512);

    const int batch = blockIdx.x >> 7;      // 128 blocks per batch
    const int warp  = threadIdx.x >> 5;     // 8 warps = 8 queries / block
    const int lane  = threadIdx.x & 31;

    const float* bp = pts + batch * N_ * 3;
    for (int i = threadIdx.x; i < N_; i += blockDim.x) {
        sx[i] = bp[i * 3 + 0];
        sy[i] = bp[i * 3 + 1];
        sz[i] = bp[i * 3 + 2];
    }
    {
        int base = ((blockIdx.x & 127) << 3) * 3;
        if (threadIdx.x < 24)
            out[batch * P_ * 3 + base + threadIdx.x] = bp[base + threadIdx.x];
    }
    __syncthreads();

    const int p = ((blockIdx.x & 127) << 3) + warp;
    const float qx = sx[p], qy = sy[p], qz = sz[p];
    const float qn = __fadd_rn(__fadd_rn(__fmul_rn(qx, qx), __fmul_rn(qy, qy)),
                               __fmul_rn(qz, qz));

    float* wbd = bufd + warp * 64;
    int*   wbi = bufi + warp * 64;

    float ld = CUDART_INF_F;     // resident sorted list: lane l = rank l
    int   li = 0x7fffffff;
    float thr_d = CUDART_INF_F;  // broadcast rank-31 (refreshed per flush)
    int   thr_i = 0x7fffffff;
    int   bufcnt = 0;
    const unsigned FULL = 0xffffffffu;

    #pragma unroll 1
    for (int r = 0; r < N_ / 32; r++) {
        int n = (r << 5) + lane;
        float x = sx[n], y = sy[n], z = sz[n];
        float pn = __fadd_rn(__fadd_rn(__fmul_rn(x, x), __fmul_rn(y, y)),
                             __fmul_rn(z, z));
        float dot = __fmaf_rn(qz, z, __fmaf_rn(qy, y, __fmul_rn(qx, x)));
        float d2 = __fadd_rn(__fsub_rn(qn, __fmul_rn(2.0f, dot)), pn);

        bool pass = (d2 < thr_d) || (d2 == thr_d && n < thr_i);
        unsigned mask = __ballot_sync(FULL, pass);
        if (mask) {
            if (pass) {
                int pos = bufcnt + __popc(mask & ((1u << lane) - 1u));
                wbd[pos] = d2;
                wbi[pos] = n;
            }
            bufcnt += __popc(mask);
            if (bufcnt >= 32) {
                bufcnt -= 32;
                __syncwarp(FULL);                    // STS -> LDS ordering
                float sd = wbd[bufcnt + lane];
                int   si = wbi[bufcnt + lane];
                __syncwarp(FULL);                    // LDS before later STS (WAR)
                topk_flush(ld, li, sd, si, lane);
                thr_d = __shfl_sync(FULL, ld, 31);
                thr_i = __shfl_sync(FULL, li, 31);
            }
        }
    }
    if (bufcnt > 0) {                                // final partial flush (pad inf)
        __syncwarp(FULL);
        float sd = (lane < bufcnt) ? wbd[lane] : CUDART_INF_F;
        int   si = (lane < bufcnt) ? wbi[lane] : 0x7fffffff;
        topk_flush(ld, li, sd, si, lane);
    }
    // dilation D=2: keep even ranks 0,2,...,30
    if (!(lane & 1))
        g_idx[(batch * P_ + p) * K_ + (lane >> 1)] = li;
}

// ---------------------------------------------------------------------------
// Fused MLP chain, M_=4 points per block, 256 threads, 5 blocks/SM.
// R14: stage H split by point across both thread-halves (per-output
// accumulation order unchanged -> bit-identical numerics).
// ---------------------------------------------------------------------------
__device__ __forceinline__ float elu_f(float x) {
    return x > 0.0f ? x : expm1f(x);
}

struct PSmem {
    int   idx[M_][K_];            // 256 B
    float local[M_][K_ * 3];      // 768 B  (rows 192 B, 16B-aligned)
    float nnin[M_][K_][CF_];      // 24 KB   cols [0:32)=f, [32:96)=features
    float h0[M_][K_][CPF_];       // 8 KB   (rows 128 B)
    float xa[M_][KK_];            // 4 KB   (rows 1024 B)
    float xb[M_][KK_];            // 4 KB
    float t[M_][CF_ * DM_];       // 3 KB   (rows 768 B)
};                                // ~44.3 KB -> 5 blocks/SM

__global__ __launch_bounds__(PT_, 5) void point_kernel(
    const float* __restrict__ pts,    const float* __restrict__ features,
    const float* __restrict__ w_fts0, const float* __restrict__ bn_fts0,
    const float* __restrict__ w_fts1, const float* __restrict__ bn_fts1,
    const float* __restrict__ w_x0,   const float* __restrict__ bn_x0,
    const float* __restrict__ w_x1,   const float* __restrict__ bn_x1,
    const float* __restrict__ w_x2,   const float* __restrict__ bn_x2,
    const float* __restrict__ w_dw,   const float* __restrict__ w_pw,
    const float* __restrict__ bn_sep, float* __restrict__ out)
{
    extern __shared__ char smem_raw[];
    PSmem& S = *reinterpret_cast<PSmem*>(smem_raw);

    const int tid = threadIdx.x;
    const int b   = blockIdx.x >> 8;               // 256 blocks per batch
    const int pq0 = (blockIdx.x & 255) * M_;       // first query idx in batch
    const int pg0 = blockIdx.x * M_;               // first global point idx

    if (tid < M_ * K_)
        S.idx[tid >> 4][tid & 15] = g_idx[pg0 * K_ + tid];
    __syncthreads();

    const float* bpts = pts + b * N_ * 3;
    if (tid < M_ * 48) {                     // 192 <= 256 threads: single pass
        int p = tid / 48, r = tid - p * 48;
        int k = r / 3, c = r - 3 * k;
        S.local[p][r] = bpts[S.idx[p][k] * 3 + c] - bpts[(pq0 + p) * 3 + c];
    }
    // features: float4 loads (F_=64 -> 16 float4 per neighbor row)
    const float4* bft4 = (const float4*)(features + b * N_ * F_);
    for (int e = tid; e < M_ * K_ * (F_ / 4); e += PT_) {
        int p = e >> 8, k = (e >> 4) & 15, f4 = e & 15;
        float4 v = __ldg(bft4 + S.idx[p][k] * (F_ / 4) + f4);
        *(float4*)&S.nnin[p][k][CPF_ + f4 * 4] = v;
    }
    __syncthreads();

    // stage A: h0 = bn0(elu(local @ w_fts0))   (M x 16 x 32)
    for (int e = tid; e < K_ * CPF_; e += PT_) {
        int k = e >> 5, j = e & 31;
        float w0 = __ldg(w_fts0 + 0 * CPF_ + j);
        float w1 = __ldg(w_fts0 + 1 * CPF_ + j);
        float w2 = __ldg(w_fts0 + 2 * CPF_ + j);
        float g  = __ldg(bn_fts0 + j);
        float bb = __ldg(bn_fts0 + CPF_ + j);
        float mm = __ldg(bn_fts0 + 2 * CPF_ + j);
        float vv = __ldg(bn_fts0 + 3 * CPF_ + j);
        float rs = __fdiv_rn(1.0f, __fsqrt_rn(vv + EPS_));
        #pragma unroll
        for (int p = 0; p < M_; p++) {
            float a = S.local[p][k * 3 + 0] * w0
                    + S.local[p][k * 3 + 1] * w1
                    + S.local[p][k * 3 + 2] * w2;
            S.h0[p][k][j] = (elu_f(a) - mm) * g * rs + bb;
        }
    }
    __syncthreads();

    // stage B: f = bn1(elu(h0 @ w_fts1)) -> nnin[:, :, 0:32]
    for (int e = tid; e < K_ * CPF_; e += PT_) {
        int k = e >> 5, j = e & 31;
        float acc[M_] = {0.f, 0.f, 0.f, 0.f};
        #pragma unroll
        for (int j04 = 0; j04 < CPF_ / 4; j04++) {
            float4 h[M_];
            #pragma unroll
            for (int p = 0; p < M_; p++)
                h[p] = *(const float4*)&S.h0[p][k][j04 * 4];
            #pragma unroll
            for (int jj = 0; jj < 4; jj++) {
                float w = __ldg(w_fts1 + (j04 * 4 + jj) * CPF_ + j);
                #pragma unroll
                for (int p = 0; p < M_; p++)
                    acc[p] += ((const float*)&h[p])[jj] * w;
            }
        }
        float g  = __ldg(bn_fts1 + j);
        float bb = __ldg(bn_fts1 + CPF_ + j);
        float mm = __ldg(bn_fts1 + 2 * CPF_ + j);
        float vv = __ldg(bn_fts1 + 3 * CPF_ + j);
        float rs = __fdiv_rn(1.0f, __fsqrt_rn(vv + EPS_));
        #pragma unroll
        for (int p = 0; p < M_; p++)
            S.nnin[p][k][j] = (elu_f(acc[p]) - mm) * g * rs + bb;
    }

    // stage C: x0 = bn_x0(elu(local @ w_x0))   local read as float4 blocks
    for (int e = tid; e < KK_; e += PT_) {
        float acc[M_] = {0.f, 0.f, 0.f, 0.f};
        #pragma unroll
        for (int kq = 0; kq < 12; kq++) {
            float4 lv[M_];
            #pragma unroll
            for (int p = 0; p < M_; p++)
                lv[p] = *(const float4*)&S.local[p][kq * 4];
            #pragma unroll
            for (int ii = 0; ii < 4; ii++) {
                float w = __ldg(w_x0 + (kq * 4 + ii) * KK_ + e);
                #pragma unroll
                for (int p = 0; p < M_; p++)
                    acc[p] += ((const float*)&lv[p])[ii] * w;
            }
        }
        float g  = __ldg(bn_x0 + e);
        float bb = __ldg(bn_x0 + KK_ + e);
        float mm = __ldg(bn_x0 + 2 * KK_ + e);
        float vv = __ldg(bn_x0 + 3 * KK_ + e);
        float rs = __fdiv_rn(1.0f, __fsqrt_rn(vv + EPS_));
        #pragma unroll
        for (int p = 0; p < M_; p++)
            S.xa[p][e] = (elu_f(acc[p]) - mm) * g * rs + bb;
    }
    __syncthreads();

    // stage D: x1[c][m] = bn_x1(elu(sum_k x0[k][c] * w_x1[k][c][m]))
    for (int e = tid; e < KK_; e += PT_) {
        int c = e >> 4, m = e & 15;
        float acc[M_] = {0.f, 0.f, 0.f, 0.f};
        #pragma unroll
        for (int k = 0; k < 16; k++) {
            float w = __ldg(w_x1 + (k * 16 + c) * 16 + m);
            #pragma unroll
            for (int p = 0; p < M_; p++) acc[p] += S.xa[p][k * 16 + c] * w;
        }
        float g  = __ldg(bn_x1 + e);
        float bb = __ldg(bn_x1 + KK_ + e);
        float mm = __ldg(bn_x1 + 2 * KK_ + e);
        float vv = __ldg(bn_x1 + 3 * KK_ + e);
        float rs = __fdiv_rn(1.0f, __fsqrt_rn(vv + EPS_));
        #pragma unroll
        for (int p = 0; p < M_; p++)
            S.xb[p][e] = (elu_f(acc[p]) - mm) * g * rs + bb;
    }
    __syncthreads();

    // stage E: x2[c][m] = bn_x2(sum_k x1[k][c] * w_x2[k][c][m])  (no elu)
    for (int e = tid; e < KK_; e += PT_) {
        int c = e >> 4, m = e & 15;
        float acc[M_] = {0.f, 0.f, 0.f, 0.f};
        #pragma unroll
        for (int k = 0; k < 16; k++) {
            float w = __ldg(w_x2 + (k * 16 + c) * 16 + m);
            #pragma unroll
            for (int p = 0; p < M_; p++) acc[p] += S.xb[p][k * 16 + c] * w;
        }
        float g  = __ldg(bn_x2 + e);
        float bb = __ldg(bn_x2 + KK_ + e);
        float mm = __ldg(bn_x2 + 2 * KK_ + e);
        float vv = __ldg(bn_x2 + 3 * KK_ + e);
        float rs = __fdiv_rn(1.0f, __fsqrt_rn(vv + EPS_));
        #pragma unroll
        for (int p = 0; p < M_; p++)
            S.xa[p][e] = (acc[p] - mm) * g * rs + bb;
    }
    __syncthreads();

    // stage F+G, per-(p,c) thread; xa rows read as float4 (j ascending inside k).
    for (int e = tid; e < M_ * CF_; e += PT_) {
        int p = e / CF_, c = e - p * CF_;
        float nnj[K_];
        #pragma unroll
        for (int j = 0; j < K_; j++) nnj[j] = S.nnin[p][j][c];
        float t0 = 0.0f, t1 = 0.0f;
        #pragma unroll
        for (int k = 0; k < K_; k++) {
            float fx = 0.0f;
            #pragma unroll
            for (int j4 = 0; j4 < 4; j4++) {
                float4 xv = *(const float4*)&S.xa[p][k * 16 + j4 * 4];
                fx += xv.x * nnj[j4 * 4 + 0];
                fx += xv.y * nnj[j4 * 4 + 1];
                fx += xv.z * nnj[j4 * 4 + 2];
                fx += xv.w * nnj[j4 * 4 + 3];
            }
            float2 wd = __ldg((const float2*)w_dw + k * CF_ + c);
            t0 += fx * wd.x;
            t1 += fx * wd.y;
        }
        S.t[p][c * DM_ + 0] = t0;
        S.t[p][c * DM_ + 1] = t1;
    }
    __syncthreads();

    // stage H: out[o] = bn_sep(elu(sum_i t[i] * w_pw[i][o]))
    // R14: points split across thread-halves (half 0 -> p 0,1; half 1 -> p 2,3);
    // per-output i-order unchanged -> bit-identical numerics, 2x warp parallelism.
    {
        int o    = tid & 127;
        int pbase = (tid >> 7) * 2;          // 0 or 2
        float acc0 = 0.f, acc1 = 0.f;
        #pragma unroll 4
        for (int i4 = 0; i4 < (CF_ * DM_) / 4; i4++) {
            float4 tv0 = *(const float4*)&S.t[pbase + 0][i4 * 4];
            float4 tv1 = *(const float4*)&S.t[pbase + 1][i4 * 4];
            #pragma unroll
            for (int ii = 0; ii < 4; ii++) {
                float w = __ldg(w_pw + (i4 * 4 + ii) * C_ + o);
                acc0 += ((const float*)&tv0)[ii] * w;
                acc1 += ((const float*)&tv1)[ii] * w;
            }
        }
        float g  = __ldg(bn_sep + o);
        float bb = __ldg(bn_sep + C_ + o);
        float mm = __ldg(bn_sep + 2 * C_ + o);
        float vv = __ldg(bn_sep + 3 * C_ + o);
        float rs = __fdiv_rn(1.0f, __fsqrt_rn(vv + EPS_));
        out[B_ * P_ * 3 + (pg0 + pbase + 0) * C_ + o] = (elu_f(acc0) - mm) * g * rs + bb;
        out[B_ * P_ * 3 + (pg0 + pbase + 1) * C_ + o] = (elu_f(acc1) - mm) * g * rs + bb;
    }
}

// ---------------------------------------------------------------------------
extern "C" void kernel_launch(void* const* d_in, const int* in_sizes, int n_in,
                              void* d_out, int out_size) {
    const float* pts      = (const float*)d_in[0];
    const float* features = (const float*)d_in[1];
    const float* w_fts0   = (const float*)d_in[2];
    const float* bn_fts0  = (const float*)d_in[3];
    const float* w_fts1   = (const float*)d_in[4];
    const float* bn_fts1  = (const float*)d_in[5];
    const float* w_x0     = (const float*)d_in[6];
    const float* bn_x0    = (const float*)d_in[7];
    const float* w_x1     = (const float*)d_in[8];
    const float* bn_x1    = (const float*)d_in[9];
    const float* w_x2     = (const float*)d_in[10];
    const float* bn_x2    = (const float*)d_in[11];
    const float* w_dw     = (const float*)d_in[12];
    const float* w_pw     = (const float*)d_in[13];
    const float* bn_sep   = (const float*)d_in[14];
    float* out = (float*)d_out;

    cudaFuncSetAttribute(knn_kernel, cudaFuncAttributeMaxDynamicSharedMemorySize, KNN_SMEM);
    knn_kernel<<<B_ * 128, 256, KNN_SMEM>>>(pts, out);

    cudaFuncSetAttribute(point_kernel, cudaFuncAttributeMaxDynamicSharedMemorySize,
                         (int)sizeof(PSmem));
    point_kernel<<<B_ * P_ / M_, PT_, sizeof(PSmem)>>>(pts, features,
                                   w_fts0, bn_fts0, w_fts1, bn_fts1,
                                   w_x0, bn_x0, w_x1, bn_x1, w_x2, bn_x2,
                                   w_dw, w_pw, bn_sep, out);
}

// round 15
// speedup vs baseline: 1.0450x; 1.0450x over previous
#include <cuda_runtime.h>
#include <math_constants.h>

#define B_   8
#define N_   4096
#define F_   64
#define P_   1024
#define K_   16
#define CPF_ 32
#define CF_  96      // CPF + F
#define C_   128
#define DM_  2
#define KK_  256     // K*K
#define EPS_ 0.001f
#define M_   4       // points per block in point_kernel
#define PT_  256     // point_kernel threads

#define KNN_W    16                      // warps (= queries) per knn block
#define KNN_SMEM (65536 + KNN_W * 64 * 8)

// Scratch for kNN indices (allocation-free rule: __device__ global)
__device__ int g_idx[B_ * P_ * K_];

// ---------------------------------------------------------------------------
// kNN: warp per query, batched top-32 (R13 bitonic flush, AoS float4 cache).
// FROZEN numerics: dot = k-ordered FMA chain; norms = square+reduce no FMA;
// d2 = (|q|^2 - 2*dot) + |p|^2; TOTAL ORDER = lexicographic (d2, index).
// R15: 16 warps/block (16 queries share one 64KB point cache) -> 12 warps/SMSP
// to hide shfl/ballot latency chains; selection logic unchanged from R13.
// ---------------------------------------------------------------------------
__device__ __forceinline__ bool lex_gt(float a, int ai, float b, int bi) {
    return (a > b) || (a == b && ai > bi);
}

// Sort 32 (sd,si) across lanes ascending-lex, then merge top-32 into (ld,li).
__device__ __forceinline__ void topk_flush(float& ld, int& li, float sd, int si,
                                           int lane) {
    const unsigned FULL = 0xffffffffu;
    #pragma unroll
    for (int k = 2; k <= 32; k <<= 1) {
        #pragma unroll
        for (int j = k >> 1; j > 0; j >>= 1) {
            float od = __shfl_xor_sync(FULL, sd, j);
            int   oi = __shfl_xor_sync(FULL, si, j);
            bool up    = ((lane & k) == 0);
            bool lower = ((lane & j) == 0);
            bool gt = lex_gt(sd, si, od, oi);
            bool takeOther = up ? (lower ? gt : !gt) : (lower ? !gt : gt);
            if (takeOther) { sd = od; si = oi; }
        }
    }
    {
        float rd = __shfl_xor_sync(FULL, sd, 31);
        int   ri = __shfl_xor_sync(FULL, si, 31);
        if (lex_gt(ld, li, rd, ri)) { ld = rd; li = ri; }
    }
    #pragma unroll
    for (int j = 16; j > 0; j >>= 1) {
        float od = __shfl_xor_sync(FULL, ld, j);
        int   oi = __shfl_xor_sync(FULL, li, j);
        bool lower = ((lane & j) == 0);
        bool gt = lex_gt(ld, li, od, oi);
        bool takeOther = lower ? gt : !gt;
        if (takeOther) { ld = od; li = oi; }
    }
}

__global__ __launch_bounds__(KNN_W * 32) void knn_kernel(
    const float* __restrict__ pts, float* __restrict__ out)
{
    extern __shared__ char smem_raw[];
    float4* sp   = (float4*)smem_raw;                       // 4096 x 16B = 64 KB
    float*  bufd = (float*)(smem_raw + 65536);              // KNN_W x 64
    int*    bufi = (int*)  (smem_raw + 65536 + KNN_W * 64 * 4);

    const int batch = blockIdx.x >> 6;      // 64 blocks per batch
    const int warp  = threadIdx.x >> 5;     // 16 warps = 16 queries / block
    const int lane  = threadIdx.x & 31;

    const float* bp = pts + batch * N_ * 3;
    for (int i = threadIdx.x; i < N_; i += blockDim.x) {
        float x = bp[i * 3 + 0], y = bp[i * 3 + 1], z = bp[i * 3 + 2];
        float pn = __fadd_rn(__fadd_rn(__fmul_rn(x, x), __fmul_rn(y, y)), __fmul_rn(z, z));
        sp[i] = make_float4(x, y, z, pn);
    }
    {
        int base = ((blockIdx.x & 63) << 4) * 3;   // 16 queries x 3 floats
        if (threadIdx.x < 48)
            out[batch * P_ * 3 + base + threadIdx.x] = bp[base + threadIdx.x];
    }
    __syncthreads();

    const int p = ((blockIdx.x & 63) << 4) + warp;  // query index 0..1023
    const float4 q = sp[p];

    float* wbd = bufd + warp * 64;
    int*   wbi = bufi + warp * 64;

    float ld = CUDART_INF_F;     // resident sorted list: lane l = rank l
    int   li = 0x7fffffff;
    float thr_d = CUDART_INF_F;  // broadcast rank-31 (refreshed per flush)
    int   thr_i = 0x7fffffff;
    int   bufcnt = 0;
    const unsigned FULL = 0xffffffffu;

    #pragma unroll 1
    for (int r = 0; r < N_ / 32; r++) {
        int n = (r << 5) + lane;
        float4 c = sp[n];
        float dot = __fmaf_rn(q.z, c.z, __fmaf_rn(q.y, c.y, __fmul_rn(q.x, c.x)));
        float d2 = __fadd_rn(__fsub_rn(q.w, __fmul_rn(2.0f, dot)), c.w);

        bool pass = (d2 < thr_d) || (d2 == thr_d && n < thr_i);
        unsigned mask = __ballot_sync(FULL, pass);
        if (mask) {
            if (pass) {
                int pos = bufcnt + __popc(mask & ((1u << lane) - 1u));
                wbd[pos] = d2;
                wbi[pos] = n;
            }
            bufcnt += __popc(mask);
            if (bufcnt >= 32) {
                bufcnt -= 32;
                __syncwarp(FULL);                    // STS -> LDS ordering
                float sd = wbd[bufcnt + lane];
                int   si = wbi[bufcnt + lane];
                __syncwarp(FULL);                    // LDS before later STS (WAR)
                topk_flush(ld, li, sd, si, lane);
                thr_d = __shfl_sync(FULL, ld, 31);
                thr_i = __shfl_sync(FULL, li, 31);
            }
        }
    }
    if (bufcnt > 0) {                                // final partial flush (pad inf)
        __syncwarp(FULL);
        float sd = (lane < bufcnt) ? wbd[lane] : CUDART_INF_F;
        int   si = (lane < bufcnt) ? wbi[lane] : 0x7fffffff;
        topk_flush(ld, li, sd, si, lane);
    }
    // dilation D=2: keep even ranks 0,2,...,30
    if (!(lane & 1))
        g_idx[(batch * P_ + p) * K_ + (lane >> 1)] = li;
}

// ---------------------------------------------------------------------------
// Fused MLP chain, M_=4 points per block, 256 threads, 5 blocks/SM.
// (R13 version — 96.3us, rel_err 2.287413e-07; R14 H-split reverted)
// ---------------------------------------------------------------------------
__device__ __forceinline__ float elu_f(float x) {
    return x > 0.0f ? x : expm1f(x);
}

struct PSmem {
    int   idx[M_][K_];            // 256 B
    float local[M_][K_ * 3];      // 768 B  (rows 192 B, 16B-aligned)
    float nnin[M_][K_][CF_];      // 24 KB   cols [0:32)=f, [32:96)=features
    float h0[M_][K_][CPF_];       // 8 KB   (rows 128 B)
    float xa[M_][KK_];            // 4 KB   (rows 1024 B)
    float xb[M_][KK_];            // 4 KB
    float t[M_][CF_ * DM_];       // 3 KB   (rows 768 B)
};                                // ~44.3 KB -> 5 blocks/SM

__global__ __launch_bounds__(PT_, 5) void point_kernel(
    const float* __restrict__ pts,    const float* __restrict__ features,
    const float* __restrict__ w_fts0, const float* __restrict__ bn_fts0,
    const float* __restrict__ w_fts1, const float* __restrict__ bn_fts1,
    const float* __restrict__ w_x0,   const float* __restrict__ bn_x0,
    const float* __restrict__ w_x1,   const float* __restrict__ bn_x1,
    const float* __restrict__ w_x2,   const float* __restrict__ bn_x2,
    const float* __restrict__ w_dw,   const float* __restrict__ w_pw,
    const float* __restrict__ bn_sep, float* __restrict__ out)
{
    extern __shared__ char smem_raw[];
    PSmem& S = *reinterpret_cast<PSmem*>(smem_raw);

    const int tid = threadIdx.x;
    const int b   = blockIdx.x >> 8;               // 256 blocks per batch
    const int pq0 = (blockIdx.x & 255) * M_;       // first query idx in batch
    const int pg0 = blockIdx.x * M_;               // first global point idx

    if (tid < M_ * K_)
        S.idx[tid >> 4][tid & 15] = g_idx[pg0 * K_ + tid];
    __syncthreads();

    const float* bpts = pts + b * N_ * 3;
    if (tid < M_ * 48) {                     // 192 <= 256 threads: single pass
        int p = tid / 48, r = tid - p * 48;
        int k = r / 3, c = r - 3 * k;
        S.local[p][r] = bpts[S.idx[p][k] * 3 + c] - bpts[(pq0 + p) * 3 + c];
    }
    // features: float4 loads (F_=64 -> 16 float4 per neighbor row)
    const float4* bft4 = (const float4*)(features + b * N_ * F_);
    for (int e = tid; e < M_ * K_ * (F_ / 4); e += PT_) {
        int p = e >> 8, k = (e >> 4) & 15, f4 = e & 15;
        float4 v = __ldg(bft4 + S.idx[p][k] * (F_ / 4) + f4);
        *(float4*)&S.nnin[p][k][CPF_ + f4 * 4] = v;
    }
    __syncthreads();

    // stage A: h0 = bn0(elu(local @ w_fts0))   (M x 16 x 32)
    for (int e = tid; e < K_ * CPF_; e += PT_) {
        int k = e >> 5, j = e & 31;
        float w0 = __ldg(w_fts0 + 0 * CPF_ + j);
        float w1 = __ldg(w_fts0 + 1 * CPF_ + j);
        float w2 = __ldg(w_fts0 + 2 * CPF_ + j);
        float g  = __ldg(bn_fts0 + j);
        float bb = __ldg(bn_fts0 + CPF_ + j);
        float mm = __ldg(bn_fts0 + 2 * CPF_ + j);
        float vv = __ldg(bn_fts0 + 3 * CPF_ + j);
        float rs = __fdiv_rn(1.0f, __fsqrt_rn(vv + EPS_));
        #pragma unroll
        for (int p = 0; p < M_; p++) {
            float a = S.local[p][k * 3 + 0] * w0
                    + S.local[p][k * 3 + 1] * w1
                    + S.local[p][k * 3 + 2] * w2;
            S.h0[p][k][j] = (elu_f(a) - mm) * g * rs + bb;
        }
    }
    __syncthreads();

    // stage B: f = bn1(elu(h0 @ w_fts1)) -> nnin[:, :, 0:32]
    for (int e = tid; e < K_ * CPF_; e += PT_) {
        int k = e >> 5, j = e & 31;
        float acc[M_] = {0.f, 0.f, 0.f, 0.f};
        #pragma unroll
        for (int j04 = 0; j04 < CPF_ / 4; j04++) {
            float4 h[M_];
            #pragma unroll
            for (int p = 0; p < M_; p++)
                h[p] = *(const float4*)&S.h0[p][k][j04 * 4];
            #pragma unroll
            for (int jj = 0; jj < 4; jj++) {
                float w = __ldg(w_fts1 + (j04 * 4 + jj) * CPF_ + j);
                #pragma unroll
                for (int p = 0; p < M_; p++)
                    acc[p] += ((const float*)&h[p])[jj] * w;
            }
        }
        float g  = __ldg(bn_fts1 + j);
        float bb = __ldg(bn_fts1 + CPF_ + j);
        float mm = __ldg(bn_fts1 + 2 * CPF_ + j);
        float vv = __ldg(bn_fts1 + 3 * CPF_ + j);
        float rs = __fdiv_rn(1.0f, __fsqrt_rn(vv + EPS_));
        #pragma unroll
        for (int p = 0; p < M_; p++)
            S.nnin[p][k][j] = (elu_f(acc[p]) - mm) * g * rs + bb;
    }

    // stage C: x0 = bn_x0(elu(local @ w_x0))   local read as float4 blocks
    for (int e = tid; e < KK_; e += PT_) {
        float acc[M_] = {0.f, 0.f, 0.f, 0.f};
        #pragma unroll
        for (int kq = 0; kq < 12; kq++) {
            float4 lv[M_];
            #pragma unroll
            for (int p = 0; p < M_; p++)
                lv[p] = *(const float4*)&S.local[p][kq * 4];
            #pragma unroll
            for (int ii = 0; ii < 4; ii++) {
                float w = __ldg(w_x0 + (kq * 4 + ii) * KK_ + e);
                #pragma unroll
                for (int p = 0; p < M_; p++)
                    acc[p] += ((const float*)&lv[p])[ii] * w;
            }
        }
        float g  = __ldg(bn_x0 + e);
        float bb = __ldg(bn_x0 + KK_ + e);
        float mm = __ldg(bn_x0 + 2 * KK_ + e);
        float vv = __ldg(bn_x0 + 3 * KK_ + e);
        float rs = __fdiv_rn(1.0f, __fsqrt_rn(vv + EPS_));
        #pragma unroll
        for (int p = 0; p < M_; p++)
            S.xa[p][e] = (elu_f(acc[p]) - mm) * g * rs + bb;
    }
    __syncthreads();

    // stage D: x1[c][m] = bn_x1(elu(sum_k x0[k][c] * w_x1[k][c][m]))
    for (int e = tid; e < KK_; e += PT_) {
        int c = e >> 4, m = e & 15;
        float acc[M_] = {0.f, 0.f, 0.f, 0.f};
        #pragma unroll
        for (int k = 0; k < 16; k++) {
            float w = __ldg(w_x1 + (k * 16 + c) * 16 + m);
            #pragma unroll
            for (int p = 0; p < M_; p++) acc[p] += S.xa[p][k * 16 + c] * w;
        }
        float g  = __ldg(bn_x1 + e);
        float bb = __ldg(bn_x1 + KK_ + e);
        float mm = __ldg(bn_x1 + 2 * KK_ + e);
        float vv = __ldg(bn_x1 + 3 * KK_ + e);
        float rs = __fdiv_rn(1.0f, __fsqrt_rn(vv + EPS_));
        #pragma unroll
        for (int p = 0; p < M_; p++)
            S.xb[p][e] = (elu_f(acc[p]) - mm) * g * rs + bb;
    }
    __syncthreads();

    // stage E: x2[c][m] = bn_x2(sum_k x1[k][c] * w_x2[k][c][m])  (no elu)
    for (int e = tid; e < KK_; e += PT_) {
        int c = e >> 4, m = e & 15;
        float acc[M_] = {0.f, 0.f, 0.f, 0.f};
        #pragma unroll
        for (int k = 0; k < 16; k++) {
            float w = __ldg(w_x2 + (k * 16 + c) * 16 + m);
            #pragma unroll
            for (int p = 0; p < M_; p++) acc[p] += S.xb[p][k * 16 + c] * w;
        }
        float g  = __ldg(bn_x2 + e);
        float bb = __ldg(bn_x2 + KK_ + e);
        float mm = __ldg(bn_x2 + 2 * KK_ + e);
        float vv = __ldg(bn_x2 + 3 * KK_ + e);
        float rs = __fdiv_rn(1.0f, __fsqrt_rn(vv + EPS_));
        #pragma unroll
        for (int p = 0; p < M_; p++)
            S.xa[p][e] = (acc[p] - mm) * g * rs + bb;
    }
    __syncthreads();

    // stage F+G, per-(p,c) thread; xa rows read as float4 (j ascending inside k).
    for (int e = tid; e < M_ * CF_; e += PT_) {
        int p = e / CF_, c = e - p * CF_;
        float nnj[K_];
        #pragma unroll
        for (int j = 0; j < K_; j++) nnj[j] = S.nnin[p][j][c];
        float t0 = 0.0f, t1 = 0.0f;
        #pragma unroll
        for (int k = 0; k < K_; k++) {
            float fx = 0.0f;
            #pragma unroll
            for (int j4 = 0; j4 < 4; j4++) {
                float4 xv = *(const float4*)&S.xa[p][k * 16 + j4 * 4];
                fx += xv.x * nnj[j4 * 4 + 0];
                fx += xv.y * nnj[j4 * 4 + 1];
                fx += xv.z * nnj[j4 * 4 + 2];
                fx += xv.w * nnj[j4 * 4 + 3];
            }
            float2 wd = __ldg((const float2*)w_dw + k * CF_ + c);
            t0 += fx * wd.x;
            t1 += fx * wd.y;
        }
        S.t[p][c * DM_ + 0] = t0;
        S.t[p][c * DM_ + 1] = t1;
    }
    __syncthreads();

    // stage H: out[o] = bn_sep(elu(sum_i t[i] * w_pw[i][o]))
    if (tid < C_) {
        int o = tid;
        float acc[M_] = {0.f, 0.f, 0.f, 0.f};
        #pragma unroll 4
        for (int i4 = 0; i4 < (CF_ * DM_) / 4; i4++) {
            float4 tv[M_];
            #pragma unroll
            for (int p = 0; p < M_; p++)
                tv[p] = *(const float4*)&S.t[p][i4 * 4];
            #pragma unroll
            for (int ii = 0; ii < 4; ii++) {
                float w = __ldg(w_pw + (i4 * 4 + ii) * C_ + o);
                #pragma unroll
                for (int p = 0; p < M_; p++)
                    acc[p] += ((const float*)&tv[p])[ii] * w;
            }
        }
        float g  = __ldg(bn_sep + o);
        float bb = __ldg(bn_sep + C_ + o);
        float mm = __ldg(bn_sep + 2 * C_ + o);
        float vv = __ldg(bn_sep + 3 * C_ + o);
        float rs = __fdiv_rn(1.0f, __fsqrt_rn(vv + EPS_));
        #pragma unroll
        for (int p = 0; p < M_; p++)
            out[B_ * P_ * 3 + (pg0 + p) * C_ + o] = (elu_f(acc[p]) - mm) * g * rs + bb;
    }
}

// ---------------------------------------------------------------------------
extern "C" void kernel_launch(void* const* d_in, const int* in_sizes, int n_in,
                              void* d_out, int out_size) {
    const float* pts      = (const float*)d_in[0];
    const float* features = (const float*)d_in[1];
    const float* w_fts0   = (const float*)d_in[2];
    const float* bn_fts0  = (const float*)d_in[3];
    const float* w_fts1   = (const float*)d_in[4];
    const float* bn_fts1  = (const float*)d_in[5];
    const float* w_x0     = (const float*)d_in[6];
    const float* bn_x0    = (const float*)d_in[7];
    const float* w_x1     = (const float*)d_in[8];
    const float* bn_x1    = (const float*)d_in[9];
    const float* w_x2     = (const float*)d_in[10];
    const float* bn_x2    = (const float*)d_in[11];
    const float* w_dw     = (const float*)d_in[12];
    const float* w_pw     = (const float*)d_in[13];
    const float* bn_sep   = (const float*)d_in[14];
    float* out = (float*)d_out;

    cudaFuncSetAttribute(knn_kernel, cudaFuncAttributeMaxDynamicSharedMemorySize, KNN_SMEM);
    knn_kernel<<<B_ * (P_ / KNN_W), KNN_W * 32, KNN_SMEM>>>(pts, out);

    cudaFuncSetAttribute(point_kernel, cudaFuncAttributeMaxDynamicSharedMemorySize,
                         (int)sizeof(PSmem));
    point_kernel<<<B_ * P_ / M_, PT_, sizeof(PSmem)>>>(pts, features,
                                   w_fts0, bn_fts0, w_fts1, bn_fts1,
                                   w_x0, bn_x0, w_x1, bn_x1, w_x2, bn_x2,
                                   w_dw, w_pw, bn_sep, out);
}